// round 4
// baseline (speedup 1.0000x reference)
#include <cuda_runtime.h>
#include <cuda_bf16.h>
#include <cstdint>

#define NN 100000
#define EE 1600000
#define ETOT (EE + NN)
#define FIN 128
#define H1D 128
#define H2D 64
#define FC1D 128
#define NCLS 10
#define MM 20000
#define SLOPE 0.2f
#define NB1 ((NN + 1023) / 1024)

// ---------------- scratch (device globals; no allocations allowed) ----------
__device__ int g_is64;
__device__ int g_es[EE];
__device__ int g_ed[EE];
__device__ int g_maskbuf[MM];
__device__ int g_cnt[NN];
__device__ int g_rowptr[NN + 1];
__device__ int g_cursor[NN];
__device__ int g_col[ETOT];
__device__ int g_bsum[NB1];
__device__ float g_h[(size_t)NN * H1D];
__device__ float g_out1[(size_t)NN * H1D];
__device__ float g_out2[(size_t)NN * H2D];
__device__ float g_as[NN];
__device__ float g_ad[NN];
__device__ float g_m[NN];
__device__ float g_iz[NN];

// ---------------- mma helpers (sm_80-portable HMMA path) ---------------------
__device__ __forceinline__ uint32_t smem_to_u32(const void* p) {
    uint32_t a;
    asm("{ .reg .u64 t; cvta.to.shared.u64 t, %1; cvt.u32.u64 %0, t; }" : "=r"(a) : "l"(p));
    return a;
}
__device__ __forceinline__ void ldsm_x4(uint32_t* r, uint32_t addr) {
    asm volatile("ldmatrix.sync.aligned.m8n8.x4.shared.b16 {%0,%1,%2,%3}, [%4];"
        : "=r"(r[0]), "=r"(r[1]), "=r"(r[2]), "=r"(r[3]) : "r"(addr));
}
__device__ __forceinline__ void ldsm_x4_t(uint32_t* r, uint32_t addr) {
    asm volatile("ldmatrix.sync.aligned.m8n8.x4.trans.shared.b16 {%0,%1,%2,%3}, [%4];"
        : "=r"(r[0]), "=r"(r[1]), "=r"(r[2]), "=r"(r[3]) : "r"(addr));
}
__device__ __forceinline__ void mma_bf16(float* c, const uint32_t* a, uint32_t b0, uint32_t b1) {
    asm volatile(
        "mma.sync.aligned.m16n8k16.row.col.f32.bf16.bf16.f32 "
        "{%0,%1,%2,%3}, {%4,%5,%6,%7}, {%8,%9}, {%0,%1,%2,%3};"
        : "+f"(c[0]), "+f"(c[1]), "+f"(c[2]), "+f"(c[3])
        : "r"(a[0]), "r"(a[1]), "r"(a[2]), "r"(a[3]), "r"(b0), "r"(b1));
}
__device__ __forceinline__ uint32_t pack2bf(float x, float y) {
    __nv_bfloat162 h = __floats2bfloat162_rn(x, y);
    return *reinterpret_cast<uint32_t*>(&h);
}

// ---------------- CSR build ---------------------------------------------------
// zero g_cnt; thread 0 also detects int64 vs int32 edges
__global__ void zero_detect_kernel(const void* edges) {
    int i = blockIdx.x * blockDim.x + threadIdx.x;
    if (i < NN) g_cnt[i] = 0;
    if (i == 0) {
        const int* q = (const int*)edges;
        int is64 = 1;
        for (int j = 0; j < 8; j++)
            if (q[2 * j + 1] != 0) is64 = 0;
        g_is64 = is64;
    }
}

// convert edges+mask to int32 scratch AND histogram dst counts
__global__ void convert_hist_kernel(const void* edges, const void* mask) {
    int i = blockIdx.x * blockDim.x + threadIdx.x;
    if (i < EE) {
        int s, d;
        if (g_is64) {
            const long long* e = (const long long*)edges;
            s = (int)e[i];
            d = (int)e[EE + i];
        } else {
            const int* e = (const int*)edges;
            s = e[i];
            d = e[EE + i];
        }
        g_es[i] = s;
        g_ed[i] = d;
        atomicAdd(&g_cnt[d], 1);
    } else if (i < EE + MM) {
        int j = i - EE;
        g_maskbuf[j] = g_is64 ? (int)((const long long*)mask)[j]
                              : ((const int*)mask)[j];
    }
}

__global__ void scan1_kernel() {
    __shared__ int sh[1024];
    int t = threadIdx.x;
    int gid = blockIdx.x * 1024 + t;
    int v = (gid < NN) ? (g_cnt[gid] + 1) : 0;   // +1 = self loop
    sh[t] = v;
    __syncthreads();
    for (int off = 1; off < 1024; off <<= 1) {
        int tv = (t >= off) ? sh[t - off] : 0;
        __syncthreads();
        sh[t] += tv;
        __syncthreads();
    }
    if (gid < NN) g_rowptr[gid] = sh[t] - v;
    if (t == 1023) g_bsum[blockIdx.x] = sh[1023];
}

__global__ void scan2_kernel() {
    __shared__ int sh[128];
    int t = threadIdx.x;
    int v = (t < NB1) ? g_bsum[t] : 0;
    sh[t] = v;
    __syncthreads();
    for (int off = 1; off < 128; off <<= 1) {
        int tv = (t >= off) ? sh[t - off] : 0;
        __syncthreads();
        sh[t] += tv;
        __syncthreads();
    }
    if (t < NB1) g_bsum[t] = sh[t] - v;
}

__global__ void scan3_kernel() {
    int gid = blockIdx.x * blockDim.x + threadIdx.x;
    if (gid < NN) {
        int r = g_rowptr[gid] + g_bsum[gid >> 10];
        g_rowptr[gid] = r;
        g_cursor[gid] = r;
    }
    if (gid == 0) g_rowptr[NN] = ETOT;
}

__global__ void scatter_kernel() {
    int i = blockIdx.x * blockDim.x + threadIdx.x;
    if (i >= ETOT) return;
    int s, d;
    if (i < EE) { s = g_es[i]; d = g_ed[i]; }
    else        { s = d = i - EE; }
    int pos = atomicAdd(&g_cursor[d], 1);
    g_col[pos] = s;
}

// ---------------- HMMA bf16-split GEMM ---------------------------------------
template <int NOUT>
__global__ __launch_bounds__(256, 1)
void mma_gemm_kernel(const float* __restrict__ A, const float* __restrict__ W,
                     float* __restrict__ C, int nrows) {
    extern __shared__ char smem[];
    constexpr int ROWB = NOUT * 2;
    constexpr int OFF_AH = 0;
    constexpr int OFF_AL = 32768;
    constexpr int OFF_BH = 65536;
    constexpr int OFF_BL = OFF_BH + 128 * ROWB;
    constexpr int MI = (NOUT == 128) ? 2 : 1;

    const int tid = threadIdx.x;
    const int wid = tid >> 5, lane = tid & 31;
    const int row0 = blockIdx.x * 128;
    const uint32_t sbase = smem_to_u32(smem);

#pragma unroll
    for (int it = 0; it < 16; it++) {
        int idx4 = tid + it * 256;
        int r = idx4 >> 5;
        int k4 = (idx4 & 31) * 4;
        int gr = row0 + r;
        float4 v = (gr < nrows) ? *(const float4*)&A[(size_t)gr * 128 + k4]
                                : make_float4(0.f, 0.f, 0.f, 0.f);
        float hx = __bfloat162float(__float2bfloat16(v.x));
        float hy = __bfloat162float(__float2bfloat16(v.y));
        float hz = __bfloat162float(__float2bfloat16(v.z));
        float hw = __bfloat162float(__float2bfloat16(v.w));
        uint2 uh = make_uint2(pack2bf(v.x, v.y), pack2bf(v.z, v.w));
        uint2 ul = make_uint2(pack2bf(v.x - hx, v.y - hy), pack2bf(v.z - hz, v.w - hw));
        uint32_t off = (uint32_t)r * 256 + ((((k4 >> 3) ^ (r & 7)) << 4) + (k4 & 7) * 2);
        *(uint2*)(smem + OFF_AH + off) = uh;
        *(uint2*)(smem + OFF_AL + off) = ul;
    }
    {
        constexpr int QPR = NOUT / 4;
        constexpr int ITER = 128 * QPR / 256;
#pragma unroll
        for (int it = 0; it < ITER; it++) {
            int idx = tid + it * 256;
            int k = idx / QPR;
            int n4 = (idx % QPR) * 4;
            float4 v = *(const float4*)&W[(size_t)k * NOUT + n4];
            float hx = __bfloat162float(__float2bfloat16(v.x));
            float hy = __bfloat162float(__float2bfloat16(v.y));
            float hz = __bfloat162float(__float2bfloat16(v.z));
            float hw = __bfloat162float(__float2bfloat16(v.w));
            uint2 uh = make_uint2(pack2bf(v.x, v.y), pack2bf(v.z, v.w));
            uint2 ul = make_uint2(pack2bf(v.x - hx, v.y - hy), pack2bf(v.z - hz, v.w - hw));
            uint32_t off = (uint32_t)k * ROWB + ((((n4 >> 3) ^ (k & 7)) << 4) + (n4 & 7) * 2);
            *(uint2*)(smem + OFF_BH + off) = uh;
            *(uint2*)(smem + OFF_BL + off) = ul;
        }
    }
    __syncthreads();

    const int m0w = (NOUT == 128) ? (wid >> 1) * 32 : wid * 16;
    const int wn  = (NOUT == 128) ? (wid & 1) * 64 : 0;

    float acc[MI][8][4];
#pragma unroll
    for (int mi = 0; mi < MI; mi++)
#pragma unroll
        for (int nt = 0; nt < 8; nt++)
#pragma unroll
            for (int q = 0; q < 4; q++) acc[mi][nt][q] = 0.f;

    const int a_row = lane & 15;
    const int a_cadd = lane >> 4;
    const int b_row = lane & 15;
    const int b_cadd = lane >> 4;

#pragma unroll
    for (int ks = 0; ks < 8; ks++) {
        uint32_t ah[MI][4], al[MI][4];
#pragma unroll
        for (int mi = 0; mi < MI; mi++) {
            int r = m0w + mi * 16 + a_row;
            int chunk = ks * 2 + a_cadd;
            uint32_t off = (uint32_t)r * 256 + (((chunk ^ (r & 7)) & 15) << 4);
            ldsm_x4(ah[mi], sbase + OFF_AH + off);
            ldsm_x4(al[mi], sbase + OFF_AL + off);
        }
#pragma unroll
        for (int p = 0; p < 4; p++) {
            int nbase = wn + p * 16;
            int r = ks * 16 + b_row;
            int chunk = (nbase >> 3) + b_cadd;
            uint32_t off = (uint32_t)r * ROWB + (((chunk ^ (r & 7)) & (ROWB / 16 - 1)) << 4);
            uint32_t bh[4], bl[4];
            ldsm_x4_t(bh, sbase + OFF_BH + off);
            ldsm_x4_t(bl, sbase + OFF_BL + off);
#pragma unroll
            for (int mi = 0; mi < MI; mi++) {
                mma_bf16(acc[mi][2 * p],     ah[mi], bh[0], bh[1]);
                mma_bf16(acc[mi][2 * p + 1], ah[mi], bh[2], bh[3]);
                mma_bf16(acc[mi][2 * p],     ah[mi], bl[0], bl[1]);
                mma_bf16(acc[mi][2 * p + 1], ah[mi], bl[2], bl[3]);
                mma_bf16(acc[mi][2 * p],     al[mi], bh[0], bh[1]);
                mma_bf16(acc[mi][2 * p + 1], al[mi], bh[2], bh[3]);
            }
        }
    }

    const int group = lane >> 2;
    const int tc = (lane & 3) * 2;
#pragma unroll
    for (int mi = 0; mi < MI; mi++) {
        int r0 = row0 + m0w + mi * 16 + group;
        int r1 = r0 + 8;
#pragma unroll
        for (int nt = 0; nt < 8; nt++) {
            int col = wn + nt * 8 + tc;
            if (r0 < nrows)
                *(float2*)&C[(size_t)r0 * NOUT + col] = make_float2(acc[mi][nt][0], acc[mi][nt][1]);
            if (r1 < nrows)
                *(float2*)&C[(size_t)r1 * NOUT + col] = make_float2(acc[mi][nt][2], acc[mi][nt][3]);
        }
    }
}

// ---------------- per-node attention logit components (vectorized) ----------
template <int F>
__global__ void alpha_kernel(const float* __restrict__ h, const float* __restrict__ a_s,
                             const float* __restrict__ a_d) {
    constexpr int V = F / 32;
    int warp = (blockIdx.x * blockDim.x + threadIdx.x) >> 5;
    int lane = threadIdx.x & 31;
    if (warp >= NN) return;
    float s = 0.f, d = 0.f;
    if (V == 4) {
        float4 hv = *(const float4*)&h[(size_t)warp * F + lane * 4];
        float4 as4 = *(const float4*)&a_s[lane * 4];
        float4 ad4 = *(const float4*)&a_d[lane * 4];
        s = hv.x * as4.x + hv.y * as4.y + hv.z * as4.z + hv.w * as4.w;
        d = hv.x * ad4.x + hv.y * ad4.y + hv.z * ad4.z + hv.w * ad4.w;
    } else {
        float2 hv = *(const float2*)&h[(size_t)warp * F + lane * 2];
        float2 as2 = *(const float2*)&a_s[lane * 2];
        float2 ad2 = *(const float2*)&a_d[lane * 2];
        s = hv.x * as2.x + hv.y * as2.y;
        d = hv.x * ad2.x + hv.y * ad2.y;
    }
#pragma unroll
    for (int off = 16; off; off >>= 1) {
        s += __shfl_xor_sync(0xffffffffu, s, off);
        d += __shfl_xor_sync(0xffffffffu, d, off);
    }
    if (lane == 0) { g_as[warp] = s; g_ad[warp] = d; }
}

// ---------------- softmax stats: thread per node (m and 1/Z) ----------------
__global__ void softmax_stats_kernel() {
    int node = blockIdx.x * blockDim.x + threadIdx.x;
    if (node >= NN) return;
    const int beg = g_rowptr[node];
    const int end = g_rowptr[node + 1];
    const float adv = g_ad[node];
    float m = -1e30f;
    for (int i = beg; i < end; i++) {
        float e = g_as[g_col[i]] + adv;
        e = (e > 0.f) ? e : SLOPE * e;
        m = fmaxf(m, e);
    }
    float Z = 0.f;
    for (int i = beg; i < end; i++) {
        float e = g_as[g_col[i]] + adv;
        e = (e > 0.f) ? e : SLOPE * e;
        Z += __expf(e - m);
    }
    g_m[node] = m;
    g_iz[node] = 1.f / Z;
}

// ---------------- weighted gather: warp per node, vectorized, unrolled ------
template <int F>
__global__ void agg_kernel(const float* __restrict__ h, const float* __restrict__ bias,
                           float* __restrict__ out) {
    constexpr int V = F / 32;
    int node = (blockIdx.x * blockDim.x + threadIdx.x) >> 5;
    int lane = threadIdx.x & 31;
    if (node >= NN) return;
    int idx = g_rowptr[node];
    const int end = g_rowptr[node + 1];
    const float adv = g_ad[node];
    const float m = g_m[node];
    float acc[V];
#pragma unroll
    for (int j = 0; j < V; j++) acc[j] = 0.f;

    for (; idx + 2 <= end; idx += 2) {
        int s0 = g_col[idx];
        int s1 = g_col[idx + 1];
        float e0 = g_as[s0] + adv;
        float e1 = g_as[s1] + adv;
        e0 = (e0 > 0.f) ? e0 : SLOPE * e0;
        e1 = (e1 > 0.f) ? e1 : SLOPE * e1;
        float w0 = __expf(e0 - m);
        float w1 = __expf(e1 - m);
        if (V == 4) {
            float4 x0 = *(const float4*)&h[(size_t)s0 * F + lane * 4];
            float4 x1 = *(const float4*)&h[(size_t)s1 * F + lane * 4];
            acc[0] += w0 * x0.x + w1 * x1.x;
            acc[1] += w0 * x0.y + w1 * x1.y;
            acc[2] += w0 * x0.z + w1 * x1.z;
            acc[3] += w0 * x0.w + w1 * x1.w;
        } else {
            float2 x0 = *(const float2*)&h[(size_t)s0 * F + lane * 2];
            float2 x1 = *(const float2*)&h[(size_t)s1 * F + lane * 2];
            acc[0] += w0 * x0.x + w1 * x1.x;
            acc[1] += w0 * x0.y + w1 * x1.y;
        }
    }
    if (idx < end) {
        int s0 = g_col[idx];
        float e0 = g_as[s0] + adv;
        e0 = (e0 > 0.f) ? e0 : SLOPE * e0;
        float w0 = __expf(e0 - m);
        if (V == 4) {
            float4 x0 = *(const float4*)&h[(size_t)s0 * F + lane * 4];
            acc[0] += w0 * x0.x; acc[1] += w0 * x0.y;
            acc[2] += w0 * x0.z; acc[3] += w0 * x0.w;
        } else {
            float2 x0 = *(const float2*)&h[(size_t)s0 * F + lane * 2];
            acc[0] += w0 * x0.x; acc[1] += w0 * x0.y;
        }
    }

    const float iz = g_iz[node];
    if (V == 4) {
        float4 b4 = *(const float4*)&bias[lane * 4];
        float4 o;
        o.x = fmaxf(acc[0] * iz + b4.x, 0.f);
        o.y = fmaxf(acc[1] * iz + b4.y, 0.f);
        o.z = fmaxf(acc[2] * iz + b4.z, 0.f);
        o.w = fmaxf(acc[3] * iz + b4.w, 0.f);
        *(float4*)&out[(size_t)node * F + lane * 4] = o;
    } else {
        float2 b2 = *(const float2*)&bias[lane * 2];
        float2 o;
        o.x = fmaxf(acc[0] * iz + b2.x, 0.f);
        o.y = fmaxf(acc[1] * iz + b2.y, 0.f);
        *(float2*)&out[(size_t)node * F + lane * 2] = o;
    }
}

// ---------------- FC head on masked nodes -----------------------------------
__global__ void fc_kernel(const float* __restrict__ feat,
                          const float* __restrict__ w1, const float* __restrict__ b1,
                          const float* __restrict__ w2, const float* __restrict__ b2,
                          float* __restrict__ out) {
    __shared__ float hm[H2D];
    __shared__ float z[FC1D];
    int mi = blockIdx.x;
    int t = threadIdx.x;
    int node = g_maskbuf[mi];
    if (t < H2D) hm[t] = feat[(size_t)node * H2D + t];
    __syncthreads();
    float acc = b1[t];
#pragma unroll
    for (int k = 0; k < H2D; k++) acc += hm[k] * w1[k * FC1D + t];
    z[t] = fmaxf(acc, 0.f);
    __syncthreads();
    if (t < NCLS) {
        float a = b2[t];
#pragma unroll
        for (int j = 0; j < FC1D; j++) a += z[j] * w2[j * NCLS + t];
        out[(size_t)mi * NCLS + t] = a;
    }
}

// ---------------- launch -----------------------------------------------------
extern "C" void kernel_launch(void* const* d_in, const int* in_sizes, int n_in,
                              void* d_out, int out_size) {
    const float* x      = (const float*)d_in[0];
    const void*  edges  = d_in[1];
    const void*  mask   = d_in[2];
    const float* W1     = (const float*)d_in[3];
    const float* a_src1 = (const float*)d_in[4];
    const float* a_dst1 = (const float*)d_in[5];
    const float* b1     = (const float*)d_in[6];
    const float* W2     = (const float*)d_in[7];
    const float* a_src2 = (const float*)d_in[8];
    const float* a_dst2 = (const float*)d_in[9];
    const float* b2     = (const float*)d_in[10];
    const float* fc1_w  = (const float*)d_in[11];
    const float* fc1_b  = (const float*)d_in[12];
    const float* fc2_w  = (const float*)d_in[13];
    const float* fc2_b  = (const float*)d_in[14];
    float* out = (float*)d_out;

    float* g_h_p;     cudaGetSymbolAddress((void**)&g_h_p, g_h);
    float* g_out1_p;  cudaGetSymbolAddress((void**)&g_out1_p, g_out1);
    float* g_out2_p;  cudaGetSymbolAddress((void**)&g_out2_p, g_out2);

    const int smem128 = 65536 + 2 * 128 * 256;   // 131072
    const int smem64  = 65536 + 2 * 128 * 128;   //  98304
    cudaFuncSetAttribute(mma_gemm_kernel<128>, cudaFuncAttributeMaxDynamicSharedMemorySize, smem128);
    cudaFuncSetAttribute(mma_gemm_kernel<64>,  cudaFuncAttributeMaxDynamicSharedMemorySize, smem64);

    // ---- CSR build (dst-indexed) ----
    zero_detect_kernel<<<(NN + 255) / 256, 256>>>(edges);
    convert_hist_kernel<<<(EE + MM + 255) / 256, 256>>>(edges, mask);
    scan1_kernel<<<NB1, 1024>>>();
    scan2_kernel<<<1, 128>>>();
    scan3_kernel<<<(NN + 255) / 256, 256>>>();
    scatter_kernel<<<(ETOT + 255) / 256, 256>>>();

    const int warpBlocks = (NN * 32 + 255) / 256;
    const int nodeBlocks = (NN + 255) / 256;
    const int gemmBlocks = (NN + 127) / 128;

    // ---- GAT layer 1: 128 -> 128 ----
    mma_gemm_kernel<128><<<gemmBlocks, 256, smem128>>>(x, W1, g_h_p, NN);
    alpha_kernel<H1D><<<warpBlocks, 256>>>(g_h_p, a_src1, a_dst1);
    softmax_stats_kernel<<<nodeBlocks, 256>>>();
    agg_kernel<H1D><<<warpBlocks, 256>>>(g_h_p, b1, g_out1_p);

    // ---- GAT layer 2: 128 -> 64 ----
    mma_gemm_kernel<64><<<gemmBlocks, 256, smem64>>>(g_out1_p, W2, g_h_p, NN);
    alpha_kernel<H2D><<<warpBlocks, 256>>>(g_h_p, a_src2, a_dst2);
    softmax_stats_kernel<<<nodeBlocks, 256>>>();
    agg_kernel<H2D><<<warpBlocks, 256>>>(g_h_p, b2, g_out2_p);

    // ---- FC head on masked nodes ----
    fc_kernel<<<MM, FC1D>>>(g_out2_p, fc1_w, fc1_b, fc2_w, fc2_b, out);
}